// round 1
// baseline (speedup 1.0000x reference)
#include <cuda_runtime.h>
#include <cuda_bf16.h>
#include <stdint.h>

// my_ceil(x) = sum_{k=1..150} sigmoid(100*(x-k)) + sigmoid(100*(x+k)) - 150
//
// With R=100, any term with |x - offset| >= 0.5 saturates EXACTLY to 0.0f or
// 1.0f in fp32 (e^-50 ~ 2e-22 << ulp(1)). Offsets are integers +-1..+-150,
// spaced 1 apart, so at most ONE term is non-saturated: the one at
// r = rint(x), when 1 <= |r| <= 150. Closed form:
//
//   f(x) = n1 - n2 + corr
//   n1 = clamp(ceil(x)-1, 0, 150)     // #{k in [1,150] : k < x}
//   n2 = clamp(floor(-x), 0, 150)     // #{k in [1,150] : -k < x} minus 150
//   corr = sigmoid(100*(x-r)) - (x > r ? 1 : 0), gated on 1<=|r|<=150
//
// This matches the 300-term fp32 scan to ~1e-7 abs (saturated 1.0 adds are
// exact in the reference too), far inside the 1e-3 rel-err gate.

__device__ __forceinline__ float my_ceil_fast(float v) {
    float n1 = fminf(fmaxf(ceilf(v) - 1.0f, 0.0f), 150.0f);
    float n2 = fminf(fmaxf(floorf(-v), 0.0f), 150.0f);
    float f  = n1 - n2;

    float r = rintf(v);
    float a = fabsf(r);
    // Correction only when the nearest integer is an actual offset.
    if (a >= 1.0f && a <= 150.0f) {
        float z = 100.0f * (v - r);               // |z| <= 50
        float s = 1.0f / (1.0f + __expf(-z));     // the single live sigmoid
        float step = (v > r) ? 1.0f : 0.0f;       // already counted in n1/n2
        f += (s - step);
    }
    return f;
}

__global__ void __launch_bounds__(256)
quan_kernel(const float4* __restrict__ x4,
            const float4* __restrict__ k4,   // kernel as 3 float4s (12 floats)
            float4* __restrict__ o4,
            int n4) {
    int i = blockIdx.x * blockDim.x + threadIdx.x;
    if (i >= n4) return;

    // element base = 4*i; channel base = (4*i) % 12 = 4*(i % 3) -> float4 slot i%3
    float4 kv = k4[i % 3];
    float4 xv = x4[i];

    float4 ov;
    ov.x = my_ceil_fast(xv.x * kv.x);
    ov.y = my_ceil_fast(xv.y * kv.y);
    ov.z = my_ceil_fast(xv.z * kv.z);
    ov.w = my_ceil_fast(xv.w * kv.w);
    o4[i] = ov;
}

extern "C" void kernel_launch(void* const* d_in, const int* in_sizes, int n_in,
                              void* d_out, int out_size) {
    // Identify inputs by size: x has 25M elements, kernel has 12.
    const float* x = (const float*)d_in[0];
    const float* k = (const float*)d_in[1];
    int nx = in_sizes[0];
    if (n_in > 1 && in_sizes[0] < in_sizes[1]) {  // defensive: swapped order
        x = (const float*)d_in[1];
        k = (const float*)d_in[0];
        nx = in_sizes[1];
    }

    int n4 = nx / 4;  // 25165824 / 4 = 6291456, exact
    int threads = 256;
    int blocks = (n4 + threads - 1) / threads;
    quan_kernel<<<blocks, threads>>>((const float4*)x, (const float4*)k,
                                     (float4*)d_out, n4);
}

// round 2
// speedup vs baseline: 1.0933x; 1.0933x over previous
#include <cuda_runtime.h>
#include <cuda_bf16.h>
#include <stdint.h>

// my_ceil(x) = sum_{k=1..150} sigmoid(100*(x-k)) + sigmoid(100*(x+k)) - 150
//
// With R=100 every term with |x-offset| >= 0.5 saturates EXACTLY to 0.0f/1.0f
// in fp32. Offsets are the integers +-1..+-150, so at most ONE term is live:
// the one at r = rint(x) when 1 <= |r| <= 150. Closed form (verified R1,
// rel_err 5.9e-8):
//   c  = ceil(v)
//   f0 = clamp(c-1, 0, 150) - clamp(-c, 0, 150)
//   corr = gate * (sigmoid(100*(v-r)) - (v > r))
//   f  = f0 + corr

#define UNROLL 4
#define TPB 256

__device__ __forceinline__ float my_ceil_fast(float v) {
    float c  = ceilf(v);
    float n1 = fminf(fmaxf(c - 1.0f, 0.0f), 150.0f);
    float n2 = fminf(fmaxf(-c, 0.0f), 150.0f);

    float r  = rintf(v);
    float z  = 100.0f * (v - r);              // |z| <= 50
    float s  = 1.0f / (1.0f + __expf(-z));    // single live sigmoid
    float step = (v > r) ? 1.0f : 0.0f;
    float ar = fabsf(r);
    float corr = (ar >= 1.0f && ar <= 150.0f) ? (s - step) : 0.0f;
    return (n1 - n2) + corr;
}

__device__ __forceinline__ float4 apply4(float4 xv, float4 kv) {
    float4 ov;
    ov.x = my_ceil_fast(xv.x * kv.x);
    ov.y = my_ceil_fast(xv.y * kv.y);
    ov.z = my_ceil_fast(xv.z * kv.z);
    ov.w = my_ceil_fast(xv.w * kv.w);
    return ov;
}

__global__ void __launch_bounds__(TPB)
quan_kernel(const float4* __restrict__ x4,
            const float4* __restrict__ k4,   // kernel as 3 float4s (12 floats)
            float4* __restrict__ o4,
            int n4) {
    int base = blockIdx.x * (TPB * UNROLL) + threadIdx.x;

    // ---- batched, fully coalesced loads (MLP_p1 = UNROLL) ----
    float4 xv[UNROLL];
    bool   ok[UNROLL];
#pragma unroll
    for (int j = 0; j < UNROLL; j++) {
        int idx = base + j * TPB;
        ok[j] = (idx < n4);
        if (ok[j]) xv[j] = x4[idx];
    }

    // ---- kernel-slot rotation, computed ONCE per thread ----
    // float4 index idx has channel base (4*idx)%12 = 4*(idx%3) -> slot idx%3.
    // Lane stride TPB=256 == 1 (mod 3), so slot for iter j is (base%3 + j)%3.
    float4 k0 = k4[0], k1 = k4[1], k2 = k4[2];
    int s0 = base % 3;
    float4 ka = (s0 == 0) ? k0 : ((s0 == 1) ? k1 : k2);  // slot for j=0,3,...
    float4 kb = (s0 == 0) ? k1 : ((s0 == 1) ? k2 : k0);  // slot for j=1,4,...
    float4 kc = (s0 == 0) ? k2 : ((s0 == 1) ? k0 : k1);  // slot for j=2,5,...

    // ---- compute + store ----
#pragma unroll
    for (int j = 0; j < UNROLL; j++) {
        float4 kv = (j % 3 == 0) ? ka : ((j % 3 == 1) ? kb : kc);
        int idx = base + j * TPB;
        if (ok[j]) o4[idx] = apply4(xv[j], kv);
    }
}

extern "C" void kernel_launch(void* const* d_in, const int* in_sizes, int n_in,
                              void* d_out, int out_size) {
    const float* x = (const float*)d_in[0];
    const float* k = (const float*)d_in[1];
    int nx = in_sizes[0];
    if (n_in > 1 && in_sizes[0] < in_sizes[1]) {  // defensive: swapped order
        x = (const float*)d_in[1];
        k = (const float*)d_in[0];
        nx = in_sizes[1];
    }

    int n4 = nx / 4;  // 25165824 / 4 = 6291456
    int per_block = TPB * UNROLL;                  // 1024 float4s per block
    int blocks = (n4 + per_block - 1) / per_block; // 6144 exact
    quan_kernel<<<blocks, TPB>>>((const float4*)x, (const float4*)k,
                                 (float4*)d_out, n4);
}

// round 3
// speedup vs baseline: 1.2201x; 1.1159x over previous
#include <cuda_runtime.h>
#include <cuda_bf16.h>
#include <stdint.h>

// my_ceil(x) = sum_{k=1..150} sigmoid(100*(x-k)) + sigmoid(100*(x+k)) - 150
//
// R=100 => every term with |x-offset| >= 0.5 saturates EXACTLY in fp32, so at
// most one term is live: the one at r = rint(v) when 1 <= |r| <= 150.
// Unified closed form (verified R1/R2, rel_err 5.9e-8 with exact sigmoid):
//   r    = rint(v)
//   base = clamp(r, -150, 150)
//   adj  = sigmoid(100*(v-r)) - (r>0 ? 1 : 0)      [only if 1<=|r|<=150]
//        = 0.5*tanh(50*(v-r)) + copysign(0.5, -r)
//   f    = base + gate * adj,  gate <=> | |r|-75.5 | <= 74.5
// tanh.approx.f32 abs err ~2e-4 << 1e-3 tolerance.

#define TPB 256
#define UNROLL 4

// ---- packed f32x2 helpers (sm_103a; ptxas never auto-fuses these) ----
__device__ __forceinline__ unsigned long long pack2(float a, float b) {
    unsigned long long r;
    asm("mov.b64 %0, {%1,%2};" : "=l"(r) : "f"(a), "f"(b));
    return r;
}
__device__ __forceinline__ void unpack2(unsigned long long p, float& a, float& b) {
    asm("mov.b64 {%0,%1}, %2;" : "=f"(a), "=f"(b) : "l"(p));
}
__device__ __forceinline__ unsigned long long mul2(unsigned long long a, unsigned long long b) {
    unsigned long long r; asm("mul.rn.f32x2 %0, %1, %2;" : "=l"(r) : "l"(a), "l"(b)); return r;
}
__device__ __forceinline__ unsigned long long add2(unsigned long long a, unsigned long long b) {
    unsigned long long r; asm("add.rn.f32x2 %0, %1, %2;" : "=l"(r) : "l"(a), "l"(b)); return r;
}
__device__ __forceinline__ unsigned long long fma2(unsigned long long a, unsigned long long b,
                                                   unsigned long long c) {
    unsigned long long r;
    asm("fma.rn.f32x2 %0, %1, %2, %3;" : "=l"(r) : "l"(a), "l"(b), "l"(c));
    return r;
}
__device__ __forceinline__ float tanh_fast(float x) {
    float r; asm("tanh.approx.f32 %0, %1;" : "=f"(r) : "f"(x)); return r;
}

// packed constants (both lanes same value)
#define CP  0x4B4000004B400000ull   //  12582912.0f = 2^23 + 2^22 (RNE magic)
#define CN  0xCB400000CB400000ull   // -12582912.0f
#define F50 0x4248000042480000ull   //  50.0f
#define M50 0xC2480000C2480000ull   // -50.0f

__device__ __forceinline__ float finish(float r, float w) {
    float th = tanh_fast(w);                               // MUFU.TANH
    unsigned int rb = __float_as_uint(r);
    // copysign(0.5f, -r): one LOP3
    float sgn = __uint_as_float(((rb ^ 0x80000000u) & 0x80000000u) | 0x3F000000u);
    float adj = fmaf(th, 0.5f, sgn);                       // FFMA
    float u   = fabsf(r) - 75.5f;                          // FADD (|src|)
    adj = (fabsf(u) <= 74.5f) ? adj : 0.0f;                // FSETP + FSEL
    float base = fminf(fmaxf(r, -150.0f), 150.0f);         // 2x FMNMX
    return base + adj;                                     // FADD
}

__device__ __forceinline__ float4 apply4(float4 xv, float4 kv) {
    unsigned long long xp0 = pack2(xv.x, xv.y), xp1 = pack2(xv.z, xv.w);
    unsigned long long kp0 = pack2(kv.x, kv.y), kp1 = pack2(kv.z, kv.w);

    unsigned long long vp0 = mul2(xp0, kp0);               // v = x*k (pair)
    unsigned long long vp1 = mul2(xp1, kp1);

    // r = rint(v) via RNE magic: (v + C) - C   (2 packed FADDs per pair)
    unsigned long long rp0 = add2(add2(vp0, CP), CN);
    unsigned long long rp1 = add2(add2(vp1, CP), CN);

    // w = 50*(v - r) = fma(v, 50, -50*r)
    unsigned long long wp0 = fma2(vp0, F50, mul2(rp0, M50));
    unsigned long long wp1 = fma2(vp1, F50, mul2(rp1, M50));

    float r0, r1, r2, r3, w0, w1, w2, w3;
    unpack2(rp0, r0, r1); unpack2(rp1, r2, r3);
    unpack2(wp0, w0, w1); unpack2(wp1, w2, w3);

    float4 o;
    o.x = finish(r0, w0);
    o.y = finish(r1, w1);
    o.z = finish(r2, w2);
    o.w = finish(r3, w3);
    return o;
}

__global__ void __launch_bounds__(TPB)
quan_kernel(const float4* __restrict__ x4,
            const float4* __restrict__ k4,   // kernel = 3 float4s (12 floats)
            float4* __restrict__ o4,
            int n4) {
    int base = blockIdx.x * (TPB * UNROLL) + threadIdx.x;

    // batched, fully coalesced loads (MLP_p1 = UNROLL)
    float4 xv[UNROLL];
    bool   ok[UNROLL];
#pragma unroll
    for (int j = 0; j < UNROLL; j++) {
        int idx = base + j * TPB;
        ok[j] = (idx < n4);
        if (ok[j]) xv[j] = x4[idx];
    }

    // kernel-slot rotation computed once per thread:
    // float4 idx -> slot idx%3; lane stride TPB=256 == 1 (mod 3)
    float4 k0 = k4[0], k1 = k4[1], k2 = k4[2];
    int s0 = base % 3;
    float4 ka = (s0 == 0) ? k0 : ((s0 == 1) ? k1 : k2);
    float4 kb = (s0 == 0) ? k1 : ((s0 == 1) ? k2 : k0);
    float4 kc = (s0 == 0) ? k2 : ((s0 == 1) ? k0 : k1);

#pragma unroll
    for (int j = 0; j < UNROLL; j++) {
        float4 kv = (j % 3 == 0) ? ka : ((j % 3 == 1) ? kb : kc);
        int idx = base + j * TPB;
        if (ok[j]) o4[idx] = apply4(xv[j], kv);
    }
}

extern "C" void kernel_launch(void* const* d_in, const int* in_sizes, int n_in,
                              void* d_out, int out_size) {
    const float* x = (const float*)d_in[0];
    const float* k = (const float*)d_in[1];
    int nx = in_sizes[0];
    if (n_in > 1 && in_sizes[0] < in_sizes[1]) {  // defensive: swapped order
        x = (const float*)d_in[1];
        k = (const float*)d_in[0];
        nx = in_sizes[1];
    }

    int n4 = nx / 4;                               // 6291456
    int per_block = TPB * UNROLL;                  // 1024 float4s/block
    int blocks = (n4 + per_block - 1) / per_block; // 6144
    quan_kernel<<<blocks, TPB>>>((const float4*)x, (const float4*)k,
                                 (float4*)d_out, n4);
}